// round 1
// baseline (speedup 1.0000x reference)
#include <cuda_runtime.h>
#include <cuda_bf16.h>

// Problem constants
#define BT 64
#define CH 256
#define HH 64
#define WW 64
#define JJ 17
#define NP 4
#define NPTS (BT * JJ)          // 1088 keypoints

// Scratch (allocation-free rule: __device__ globals)
__device__ float g_seed[NPTS * CH];   // [pt][c]
__device__ float g_grid[NPTS * 2 * NP]; // [pt][n][2] -> gx,gy per deformed point

// uniform 4-way select (index is warp-uniform)
__device__ __forceinline__ float sel4(float4 q, int i) {
    float r = q.x;
    if (i == 1) r = q.y;
    else if (i == 2) r = q.z;
    else if (i == 3) r = q.w;
    return r;
}

// Bilinear sample of one channel plane at normalized (gx, gy) in [-1,1],
// align_corners=True, zeros padding. plane points to features[b][c][0][0].
// Uses an aligned float4 per row to cover both x-corners (warp-uniform control).
__device__ __forceinline__ float sample_bilinear_c(
    const float* __restrict__ plane, float gx, float gy)
{
    float x = (gx + 1.0f) * 0.5f * (float)(WW - 1);
    float y = (gy + 1.0f) * 0.5f * (float)(HH - 1);
    float x0f = floorf(x), y0f = floorf(y);
    float wx1 = x - x0f, wx0 = 1.0f - wx1;
    float wy1 = y - y0f, wy0 = 1.0f - wy1;
    int x0 = (int)x0f, y0 = (int)y0f;
    int x1 = x0 + 1,   y1 = y0 + 1;

    float vx0 = (x0 >= 0 && x0 <= WW - 1) ? 1.0f : 0.0f;
    float vx1 = (x1 >= 0 && x1 <= WW - 1) ? 1.0f : 0.0f;
    float vy0 = (y0 >= 0 && y0 <= HH - 1) ? 1.0f : 0.0f;
    float vy1 = (y1 >= 0 && y1 <= HH - 1) ? 1.0f : 0.0f;

    int xc0 = min(max(x0, 0), WW - 1);
    int xc1 = min(max(x1, 0), WW - 1);
    int yc0 = min(max(y0, 0), HH - 1);
    int yc1 = min(max(y1, 0), HH - 1);

    int bc = xc0 & ~3;
    int o0 = xc0 - bc;      // 0..3
    int o1 = xc1 - bc;      // o0 or o0+1 (0..4), or ==o0 when clamped

    const float* r0 = plane + yc0 * WW;
    const float* r1 = plane + yc1 * WW;
    float4 q0 = __ldg((const float4*)(r0 + bc));
    float4 q1 = __ldg((const float4*)(r1 + bc));

    float e0 = 0.0f, e1 = 0.0f;
    if (o1 == 4) {          // warp-uniform branch
        e0 = __ldg(r0 + xc1);
        e1 = __ldg(r1 + xc1);
    }
    float v00 = sel4(q0, o0);
    float v01 = (o1 == 4) ? e0 : sel4(q0, o1);
    float v10 = sel4(q1, o0);
    float v11 = (o1 == 4) ? e1 : sel4(q1, o1);

    float w00 = wx0 * wy0 * vx0 * vy0;
    float w01 = wx1 * wy0 * vx1 * vy0;
    float w10 = wx0 * wy1 * vx0 * vy1;
    float w11 = wx1 * wy1 * vx1 * vy1;

    return v00 * w00 + v01 * w01 + v10 * w10 + v11 * w11;
}

// K0: seed sampling at keypoints. grid = NPTS blocks, 256 threads (1 channel each).
__global__ void k0_seed(const float* __restrict__ feat, const float* __restrict__ kp)
{
    int pt = blockIdx.x;            // b*JJ + j
    int c  = threadIdx.x;
    int b  = pt / JJ;
    float gx = __ldg(kp + pt * 2 + 0);
    float gy = __ldg(kp + pt * 2 + 1);
    const float* plane = feat + ((size_t)b * CH + c) * (HH * WW);
    g_seed[pt * CH + c] = sample_bilinear_c(plane, gx, gy);
}

// K1: MLP (256->128 relu ->8) + grid construction. 68 blocks x 256 threads,
// 16 points per block; each thread computes one h-row for 8 points (w1 reuse x8).
__global__ void k1_mlp(const float* __restrict__ kp,
                       const float* __restrict__ w1, const float* __restrict__ b1,
                       const float* __restrict__ w2, const float* __restrict__ b2)
{
    __shared__ float s_seed[16 * CH];     // 16 KB
    __shared__ float s_h[16 * 128];       // 8 KB
    int p0  = blockIdx.x * 16;
    int tid = threadIdx.x;

    // cooperative load of 16 points' seeds
    {
        const float4* src = (const float4*)(g_seed + (size_t)p0 * CH);
        float4* dst = (float4*)s_seed;
        #pragma unroll
        for (int i = tid; i < 16 * CH / 4; i += 256) dst[i] = src[i];
    }
    __syncthreads();

    int o = tid & 127;        // output row of w1
    int g = tid >> 7;         // which 8-point half
    float acc[8];
    #pragma unroll
    for (int p = 0; p < 8; p++) acc[p] = 0.0f;

    const float4* wrow = (const float4*)(w1 + o * CH);
    #pragma unroll 4
    for (int c4 = 0; c4 < CH / 4; c4++) {
        float4 w = __ldg(wrow + c4);
        #pragma unroll
        for (int p = 0; p < 8; p++) {
            float4 s = *(const float4*)(s_seed + (g * 8 + p) * CH + c4 * 4);
            acc[p] += w.x * s.x + w.y * s.y + w.z * s.z + w.w * s.w;
        }
    }
    float bias = __ldg(b1 + o);
    #pragma unroll
    for (int p = 0; p < 8; p++)
        s_h[(g * 8 + p) * 128 + o] = fmaxf(acc[p] + bias, 0.0f);
    __syncthreads();

    // second layer: 16 points * 8 outputs = 128 tasks
    if (tid < 128) {
        int p  = tid >> 3;
        int oo = tid & 7;
        const float4* w2r = (const float4*)(w2 + oo * 128);
        const float4* hr  = (const float4*)(s_h + p * 128);
        float a = 0.0f;
        #pragma unroll
        for (int k = 0; k < 32; k++) {
            float4 w = __ldg(w2r + k);
            float4 h = hr[k];
            a += w.x * h.x + w.y * h.y + w.z * h.z + w.w * h.w;
        }
        a += __ldg(b2 + oo);
        int pt = p0 + p;
        int d  = oo & 1;      // 0 = x (scale 2/(W-1)), 1 = y (scale 2/(H-1))
        float scale = (d == 0) ? (2.0f / (WW - 1)) : (2.0f / (HH - 1));
        float base = __ldg(kp + pt * 2 + d);
        g_grid[pt * (2 * NP) + oo] = base + a * scale;   // oo = n*2 + d
    }
}

// K2: deformable sampling + channel-last write.
// grid = NPTS blocks, 256 threads (1 channel each), loop over NP points.
__global__ void k2_sample(const float* __restrict__ feat, float* __restrict__ out)
{
    int pt = blockIdx.x;
    int c  = threadIdx.x;
    int b  = pt / JJ;
    const float* plane = feat + ((size_t)b * CH + c) * (HH * WW);
    float* obase = out + (size_t)pt * (NP * CH) + c;
    #pragma unroll
    for (int n = 0; n < NP; n++) {
        float gx = g_grid[pt * (2 * NP) + n * 2 + 0];
        float gy = g_grid[pt * (2 * NP) + n * 2 + 1];
        obase[n * CH] = sample_bilinear_c(plane, gx, gy);
    }
}

extern "C" void kernel_launch(void* const* d_in, const int* in_sizes, int n_in,
                              void* d_out, int out_size)
{
    const float* feat = (const float*)d_in[0];   // [64,256,64,64]
    const float* kp   = (const float*)d_in[1];   // [64,17,2]
    const float* w1   = (const float*)d_in[2];   // [128,256]
    const float* b1   = (const float*)d_in[3];   // [128]
    const float* w2   = (const float*)d_in[4];   // [8,128]
    const float* b2   = (const float*)d_in[5];   // [8]
    float* out = (float*)d_out;                  // [64,17,1024]

    k0_seed<<<NPTS, 256>>>(feat, kp);
    k1_mlp<<<NPTS / 16, 256>>>(kp, w1, b1, w2, b2);
    k2_sample<<<NPTS, 256>>>(feat, out);
}

// round 2
// speedup vs baseline: 1.0142x; 1.0142x over previous
#include <cuda_runtime.h>
#include <cuda_bf16.h>

// Problem constants
#define BT 64
#define CH 256
#define HH 64
#define WW 64
#define JJ 17
#define NP 4
#define NPTS (BT * JJ)          // 1088 keypoints

// Scratch (allocation-free rule: __device__ globals)
__device__ float g_seed[NPTS * CH];        // [pt][c]
__device__ float g_grid[NPTS * 2 * NP];    // [pt][n*2+d]
__device__ float g_win[NPTS * CH * 8];     // [pt][c][2 rows x 4 cols] cached corner window
__device__ int4  g_meta[NPTS];             // (yc0, yc1, bc, 0) per point

// uniform 4-way select (index is warp-uniform)
__device__ __forceinline__ float sel4(float4 q, int i) {
    float r = q.x;
    if (i == 1) r = q.y;
    else if (i == 2) r = q.z;
    else if (i == 3) r = q.w;
    return r;
}

// Full gather-based bilinear sample (fallback path / seed path).
__device__ __forceinline__ float sample_bilinear_c(
    const float* __restrict__ plane, float gx, float gy)
{
    float x = (gx + 1.0f) * 0.5f * (float)(WW - 1);
    float y = (gy + 1.0f) * 0.5f * (float)(HH - 1);
    float x0f = floorf(x), y0f = floorf(y);
    float wx1 = x - x0f, wx0 = 1.0f - wx1;
    float wy1 = y - y0f, wy0 = 1.0f - wy1;
    int x0 = (int)x0f, y0 = (int)y0f;
    int x1 = x0 + 1,   y1 = y0 + 1;

    float vx0 = (x0 >= 0 && x0 <= WW - 1) ? 1.0f : 0.0f;
    float vx1 = (x1 >= 0 && x1 <= WW - 1) ? 1.0f : 0.0f;
    float vy0 = (y0 >= 0 && y0 <= HH - 1) ? 1.0f : 0.0f;
    float vy1 = (y1 >= 0 && y1 <= HH - 1) ? 1.0f : 0.0f;

    int xc0 = min(max(x0, 0), WW - 1);
    int xc1 = min(max(x1, 0), WW - 1);
    int yc0 = min(max(y0, 0), HH - 1);
    int yc1 = min(max(y1, 0), HH - 1);

    int bc = xc0 & ~3;
    int o0 = xc0 - bc;
    int o1 = xc1 - bc;

    const float* r0 = plane + yc0 * WW;
    const float* r1 = plane + yc1 * WW;
    float4 q0 = __ldg((const float4*)(r0 + bc));
    float4 q1 = __ldg((const float4*)(r1 + bc));

    float e0 = 0.0f, e1 = 0.0f;
    if (o1 == 4) {
        e0 = __ldg(r0 + xc1);
        e1 = __ldg(r1 + xc1);
    }
    float v00 = sel4(q0, o0);
    float v01 = (o1 == 4) ? e0 : sel4(q0, o1);
    float v10 = sel4(q1, o0);
    float v11 = (o1 == 4) ? e1 : sel4(q1, o1);

    float w00 = wx0 * wy0 * vx0 * vy0;
    float w01 = wx1 * wy0 * vx1 * vy0;
    float w10 = wx0 * wy1 * vx0 * vy1;
    float w11 = wx1 * wy1 * vx1 * vy1;

    return v00 * w00 + v01 * w01 + v10 * w10 + v11 * w11;
}

// K0: seed sampling at keypoints + cache the 2x4 corner window per (pt, c).
__global__ void k0_seed(const float* __restrict__ feat, const float* __restrict__ kp)
{
    int pt = blockIdx.x;
    int c  = threadIdx.x;
    int b  = pt / JJ;
    float gx = __ldg(kp + pt * 2 + 0);
    float gy = __ldg(kp + pt * 2 + 1);

    // uniform coordinate math (same for all threads in block)
    float x = (gx + 1.0f) * 0.5f * (float)(WW - 1);
    float y = (gy + 1.0f) * 0.5f * (float)(HH - 1);
    float x0f = floorf(x), y0f = floorf(y);
    float wx1 = x - x0f, wx0 = 1.0f - wx1;
    float wy1 = y - y0f, wy0 = 1.0f - wy1;
    int x0 = (int)x0f, y0 = (int)y0f;
    int x1 = x0 + 1,   y1 = y0 + 1;

    float vx0 = (x0 >= 0 && x0 <= WW - 1) ? 1.0f : 0.0f;
    float vx1 = (x1 >= 0 && x1 <= WW - 1) ? 1.0f : 0.0f;
    float vy0 = (y0 >= 0 && y0 <= HH - 1) ? 1.0f : 0.0f;
    float vy1 = (y1 >= 0 && y1 <= HH - 1) ? 1.0f : 0.0f;

    int xc0 = min(max(x0, 0), WW - 1);
    int xc1 = min(max(x1, 0), WW - 1);
    int yc0 = min(max(y0, 0), HH - 1);
    int yc1 = min(max(y1, 0), HH - 1);

    int bc = xc0 & ~3;
    int o0 = xc0 - bc;
    int o1 = xc1 - bc;

    const float* plane = feat + ((size_t)b * CH + c) * (HH * WW);
    const float* r0 = plane + yc0 * WW;
    const float* r1 = plane + yc1 * WW;
    float4 q0 = __ldg((const float4*)(r0 + bc));
    float4 q1 = __ldg((const float4*)(r1 + bc));

    float e0 = 0.0f, e1 = 0.0f;
    if (o1 == 4) {
        e0 = __ldg(r0 + xc1);
        e1 = __ldg(r1 + xc1);
    }
    float v00 = sel4(q0, o0);
    float v01 = (o1 == 4) ? e0 : sel4(q0, o1);
    float v10 = sel4(q1, o0);
    float v11 = (o1 == 4) ? e1 : sel4(q1, o1);

    float w00 = wx0 * wy0 * vx0 * vy0;
    float w01 = wx1 * wy0 * vx1 * vy0;
    float w10 = wx0 * wy1 * vx0 * vy1;
    float w11 = wx1 * wy1 * vx1 * vy1;

    g_seed[pt * CH + c] = v00 * w00 + v01 * w01 + v10 * w10 + v11 * w11;

    // cache window (coalesced 32B/thread)
    float4* wptr = (float4*)(g_win + ((size_t)pt * CH + c) * 8);
    wptr[0] = q0;
    wptr[1] = q1;
    if (c == 0) g_meta[pt] = make_int4(yc0, yc1, bc, 0);
}

// K1: MLP (256->128 relu ->8) + grid construction. 68 blocks x 256 threads.
__global__ void k1_mlp(const float* __restrict__ kp,
                       const float* __restrict__ w1, const float* __restrict__ b1,
                       const float* __restrict__ w2, const float* __restrict__ b2)
{
    __shared__ float s_seed[16 * CH];     // 16 KB
    __shared__ float s_h[16 * 128];       // 8 KB
    int p0  = blockIdx.x * 16;
    int tid = threadIdx.x;

    {
        const float4* src = (const float4*)(g_seed + (size_t)p0 * CH);
        float4* dst = (float4*)s_seed;
        #pragma unroll
        for (int i = tid; i < 16 * CH / 4; i += 256) dst[i] = src[i];
    }
    __syncthreads();

    int o = tid & 127;
    int g = tid >> 7;
    float acc[8];
    #pragma unroll
    for (int p = 0; p < 8; p++) acc[p] = 0.0f;

    const float4* wrow = (const float4*)(w1 + o * CH);
    #pragma unroll 4
    for (int c4 = 0; c4 < CH / 4; c4++) {
        float4 w = __ldg(wrow + c4);
        #pragma unroll
        for (int p = 0; p < 8; p++) {
            float4 s = *(const float4*)(s_seed + (g * 8 + p) * CH + c4 * 4);
            acc[p] += w.x * s.x + w.y * s.y + w.z * s.z + w.w * s.w;
        }
    }
    float bias = __ldg(b1 + o);
    #pragma unroll
    for (int p = 0; p < 8; p++)
        s_h[(g * 8 + p) * 128 + o] = fmaxf(acc[p] + bias, 0.0f);
    __syncthreads();

    if (tid < 128) {
        int p  = tid >> 3;
        int oo = tid & 7;
        const float4* w2r = (const float4*)(w2 + oo * 128);
        const float4* hr  = (const float4*)(s_h + p * 128);
        float a = 0.0f;
        #pragma unroll
        for (int k = 0; k < 32; k++) {
            float4 w = __ldg(w2r + k);
            float4 h = hr[k];
            a += w.x * h.x + w.y * h.y + w.z * h.z + w.w * h.w;
        }
        a += __ldg(b2 + oo);
        int pt = p0 + p;
        int d  = oo & 1;
        float scale = (d == 0) ? (2.0f / (WW - 1)) : (2.0f / (HH - 1));
        float base = __ldg(kp + pt * 2 + d);
        g_grid[pt * (2 * NP) + oo] = base + a * scale;
    }
}

// K2: deformable sampling from the cached window (fast path, block-uniform)
// with gather fallback when the deformed corners leave the window.
__global__ void k2_sample(const float* __restrict__ feat, float* __restrict__ out)
{
    int pt = blockIdx.x;
    int c  = threadIdx.x;
    int b  = pt / JJ;

    int4 meta = g_meta[pt];
    int syc0 = meta.x, syc1 = meta.y, sbc = meta.z;

    const float4* wptr = (const float4*)(g_win + ((size_t)pt * CH + c) * 8);
    float4 q0 = wptr[0];
    float4 q1 = wptr[1];

    const float* plane = feat + ((size_t)b * CH + c) * (HH * WW);
    float* obase = out + (size_t)pt * (NP * CH) + c;

    #pragma unroll
    for (int n = 0; n < NP; n++) {
        float gx = __ldg(&g_grid[pt * (2 * NP) + n * 2 + 0]);
        float gy = __ldg(&g_grid[pt * (2 * NP) + n * 2 + 1]);

        float x = (gx + 1.0f) * 0.5f * (float)(WW - 1);
        float y = (gy + 1.0f) * 0.5f * (float)(HH - 1);
        float x0f = floorf(x), y0f = floorf(y);
        float wx1 = x - x0f, wx0 = 1.0f - wx1;
        float wy1 = y - y0f, wy0 = 1.0f - wy1;
        int x0 = (int)x0f, y0 = (int)y0f;
        int x1 = x0 + 1,   y1 = y0 + 1;

        float vx0 = (x0 >= 0 && x0 <= WW - 1) ? 1.0f : 0.0f;
        float vx1 = (x1 >= 0 && x1 <= WW - 1) ? 1.0f : 0.0f;
        float vy0 = (y0 >= 0 && y0 <= HH - 1) ? 1.0f : 0.0f;
        float vy1 = (y1 >= 0 && y1 <= HH - 1) ? 1.0f : 0.0f;

        int xc0 = min(max(x0, 0), WW - 1);
        int xc1 = min(max(x1, 0), WW - 1);
        int yc0 = min(max(y0, 0), HH - 1);
        int yc1 = min(max(y1, 0), HH - 1);

        bool fast = (yc0 == syc0 || yc0 == syc1)
                 && (yc1 == syc0 || yc1 == syc1)
                 && (xc0 >= sbc) && (xc1 <= sbc + 3);

        float r;
        if (fast) {   // block-uniform branch (coords uniform per pt)
            float4 ra = (yc0 == syc0) ? q0 : q1;
            float4 rb = (yc1 == syc0) ? q0 : q1;
            float v00 = sel4(ra, xc0 - sbc);
            float v01 = sel4(ra, xc1 - sbc);
            float v10 = sel4(rb, xc0 - sbc);
            float v11 = sel4(rb, xc1 - sbc);
            float w00 = wx0 * wy0 * vx0 * vy0;
            float w01 = wx1 * wy0 * vx1 * vy0;
            float w10 = wx0 * wy1 * vx0 * vy1;
            float w11 = wx1 * wy1 * vx1 * vy1;
            r = v00 * w00 + v01 * w01 + v10 * w10 + v11 * w11;
        } else {
            r = sample_bilinear_c(plane, gx, gy);
        }
        obase[n * CH] = r;
    }
}

extern "C" void kernel_launch(void* const* d_in, const int* in_sizes, int n_in,
                              void* d_out, int out_size)
{
    const float* feat = (const float*)d_in[0];   // [64,256,64,64]
    const float* kp   = (const float*)d_in[1];   // [64,17,2]
    const float* w1   = (const float*)d_in[2];   // [128,256]
    const float* b1   = (const float*)d_in[3];   // [128]
    const float* w2   = (const float*)d_in[4];   // [8,128]
    const float* b2   = (const float*)d_in[5];   // [8]
    float* out = (float*)d_out;                  // [64,17,1024]

    k0_seed<<<NPTS, 256>>>(feat, kp);
    k1_mlp<<<NPTS / 16, 256>>>(kp, w1, b1, w2, b2);
    k2_sample<<<NPTS, 256>>>(feat, out);
}